// round 1
// baseline (speedup 1.0000x reference)
#include <cuda_runtime.h>

#define N_NODES 100000
#define N_EDGES 1600000
#define D_FEAT  64

// Persistent scratch (no allocations allowed in kernel_launch).
__device__ float g_agg[N_NODES * D_FEAT];   // segment-sum accumulator
__device__ float g_h1 [N_NODES * D_FEAT];   // layer-1 output
__device__ float g_deg[N_NODES];            // in-degree per node

// ---------------------------------------------------------------------------
// Zero the aggregation buffer (and degree buffer on the first pass).
// ---------------------------------------------------------------------------
__global__ void zero_kernel(int with_deg) {
    int i = blockIdx.x * blockDim.x + threadIdx.x;   // 0 .. N_NODES*16-1
    if (i < N_NODES * (D_FEAT / 4)) {
        ((float4*)g_agg)[i] = make_float4(0.f, 0.f, 0.f, 0.f);
    }
    if (with_deg && i < N_NODES) {
        g_deg[i] = 0.f;
    }
}

// ---------------------------------------------------------------------------
// Degree: one float atomic per edge (no return value -> REDG).
// ---------------------------------------------------------------------------
__global__ void deg_kernel(const int* __restrict__ dst) {
    int e = blockIdx.x * blockDim.x + threadIdx.x;
    if (e < N_EDGES) {
        atomicAdd(&g_deg[dst[e]], 1.0f);
    }
}

// ---------------------------------------------------------------------------
// Edge-parallel aggregation: 16 lanes per edge, each lane moves one float4.
// Gather x[src] (L2-resident), vector red.add to agg[dst].
// ---------------------------------------------------------------------------
template <bool LAYER1>
__global__ void agg_kernel(const float4* __restrict__ xin,
                           const int* __restrict__ src,
                           const int* __restrict__ dst) {
    const float4* x4 = LAYER1 ? xin : (const float4*)g_h1;
    int i = blockIdx.x * blockDim.x + threadIdx.x;   // E*16 = 25.6M threads
    int e = i >> 4;
    int c = i & 15;
    if (e < N_EDGES) {
        int s = __ldg(&src[e]);
        int d = __ldg(&dst[e]);
        float4 v = __ldg(&x4[s * 16 + c]);
        float* p = (float*)&(((float4*)g_agg)[d * 16 + c]);
        asm volatile("red.global.add.v4.f32 [%0], {%1,%2,%3,%4};"
                     :: "l"(p), "f"(v.x), "f"(v.y), "f"(v.z), "f"(v.w)
                     : "memory");
    }
}

// ---------------------------------------------------------------------------
// Fused layer: out = act( X @ Wself^T + (agg/max(deg,1)) @ Wneigh^T + b )
// Tile: 64 rows x 64 cols per CTA of 256 threads.
// Two K-phases (self, neigh) sharing the same shared-memory tiles.
// Each thread: 4 rows x 4 cols, float4 vectorized over k.
// ---------------------------------------------------------------------------
#define FMA4(ACC, A, WV)                         \
    (ACC).x = fmaf((A), (WV).x, (ACC).x);        \
    (ACC).y = fmaf((A), (WV).y, (ACC).y);        \
    (ACC).z = fmaf((A), (WV).z, (ACC).z);        \
    (ACC).w = fmaf((A), (WV).w, (ACC).w);

template <bool LAYER1>
__global__ void __launch_bounds__(256)
sage_gemm(const float* __restrict__ Xin,
          const float* __restrict__ Wself,
          const float* __restrict__ Wneigh,
          const float* __restrict__ bias,
          float* __restrict__ outp) {
    const float* X   = LAYER1 ? Xin : (const float*)g_h1;
    float*       out = LAYER1 ? (float*)g_h1 : outp;

    __shared__ float sW[64 * 64];        // W^T tile: sW[k*64 + j] = W[j][k]
    __shared__ float sA[64 * 68];        // A tile, padded row stride 68
    __shared__ float sRinv[64];
    __shared__ float sB[64];

    const int tid  = threadIdx.x;
    const int row0 = blockIdx.x * 64;
    const int tx   = tid & 15;           // col group: cols tx*4 .. tx*4+3
    const int ty   = tid >> 4;           // row base: rows ty + 16*i

    if (tid < 64) {
        int r = row0 + tid;
        float dg = (r < N_NODES) ? g_deg[r] : 1.0f;
        sRinv[tid] = 1.0f / fmaxf(dg, 1.0f);
        sB[tid] = bias[tid];
    }

    float4 acc[4];
#pragma unroll
    for (int i = 0; i < 4; i++) acc[i] = make_float4(0.f, 0.f, 0.f, 0.f);

#pragma unroll 1
    for (int ph = 0; ph < 2; ph++) {
        __syncthreads();   // protect sW/sA reuse across phases

        // Load W transposed into shared: sW[k*64+j] = W[j*64+k]
        const float* W = (ph == 0) ? Wself : Wneigh;
#pragma unroll
        for (int l = 0; l < 16; l++) {
            int idx = tid + l * 256;     // 0..4095
            int k = idx >> 6, j = idx & 63;
            sW[k * 64 + j] = __ldg(&W[j * 64 + k]);
        }

        // Load A tile (64 rows x 16 float4), scaled by 1/deg in phase 1.
        const float4* src4 = (ph == 0) ? (const float4*)X : (const float4*)g_agg;
#pragma unroll
        for (int l = 0; l < 4; l++) {
            int idx = tid + l * 256;     // 0..1023
            int row = idx >> 4, f = idx & 15;
            int gr = row0 + row;
            float4 v = make_float4(0.f, 0.f, 0.f, 0.f);
            if (gr < N_NODES) v = __ldg(&src4[gr * 16 + f]);
            if (ph == 1) {
                float s = sRinv[row];
                v.x *= s; v.y *= s; v.z *= s; v.w *= s;
            }
            *(float4*)(sA + row * 68 + f * 4) = v;
        }
        __syncthreads();

        // MAC loop: 64 FFMA per thread per 4-k step.
#pragma unroll 4
        for (int k = 0; k < 64; k += 4) {
            float4 wv0 = *(const float4*)(sW + (k + 0) * 64 + tx * 4);
            float4 wv1 = *(const float4*)(sW + (k + 1) * 64 + tx * 4);
            float4 wv2 = *(const float4*)(sW + (k + 2) * 64 + tx * 4);
            float4 wv3 = *(const float4*)(sW + (k + 3) * 64 + tx * 4);
#pragma unroll
            for (int i = 0; i < 4; i++) {
                int row = ty + 16 * i;
                float4 av = *(const float4*)(sA + row * 68 + k);
                FMA4(acc[i], av.x, wv0);
                FMA4(acc[i], av.y, wv1);
                FMA4(acc[i], av.z, wv2);
                FMA4(acc[i], av.w, wv3);
            }
        }
    }

    // Epilogue: + bias, optional ReLU, store float4.
    float4 bv = *(const float4*)(sB + tx * 4);
#pragma unroll
    for (int i = 0; i < 4; i++) {
        int row = ty + 16 * i;
        int gr = row0 + row;
        if (gr < N_NODES) {
            float4 o;
            o.x = acc[i].x + bv.x;
            o.y = acc[i].y + bv.y;
            o.z = acc[i].z + bv.z;
            o.w = acc[i].w + bv.w;
            if (LAYER1) {
                o.x = fmaxf(o.x, 0.f);
                o.y = fmaxf(o.y, 0.f);
                o.z = fmaxf(o.z, 0.f);
                o.w = fmaxf(o.w, 0.f);
            }
            *(float4*)(out + gr * 64 + tx * 4) = o;
        }
    }
}

// ---------------------------------------------------------------------------
// Launch: zero -> deg -> agg1 -> layer1(relu) -> zero -> agg2 -> layer2
// All on the default stream; graph capture preserves the ordering.
// ---------------------------------------------------------------------------
extern "C" void kernel_launch(void* const* d_in, const int* in_sizes, int n_in,
                              void* d_out, int out_size) {
    const float* in_feat = (const float*)d_in[0];
    const int*   src     = (const int*)d_in[1];
    const int*   dst     = (const int*)d_in[2];
    const float* Ws1     = (const float*)d_in[3];
    const float* Wn1     = (const float*)d_in[4];
    const float* b1      = (const float*)d_in[5];
    const float* Ws2     = (const float*)d_in[6];
    const float* Wn2     = (const float*)d_in[7];
    const float* b2      = (const float*)d_in[8];
    float*       out     = (float*)d_out;

    const int zero_blocks = (N_NODES * (D_FEAT / 4) + 255) / 256;   // 6250
    const int deg_blocks  = (N_EDGES + 255) / 256;                  // 6250
    const int agg_blocks  = (N_EDGES * 16) / 256;                   // 100000
    const int gemm_blocks = (N_NODES + 63) / 64;                    // 1563

    zero_kernel<<<zero_blocks, 256>>>(1);
    deg_kernel<<<deg_blocks, 256>>>(dst);
    agg_kernel<true><<<agg_blocks, 256>>>((const float4*)in_feat, src, dst);
    sage_gemm<true><<<gemm_blocks, 256>>>(in_feat, Ws1, Wn1, b1, nullptr);
    zero_kernel<<<zero_blocks, 256>>>(0);
    agg_kernel<false><<<agg_blocks, 256>>>(nullptr, src, dst);
    sage_gemm<false><<<gemm_blocks, 256>>>(nullptr, Ws2, Wn2, b2, out);
}